// round 8
// baseline (speedup 1.0000x reference)
#include <cuda_runtime.h>

#define BB 64
#define HH 16
#define DD 128
#define S_TOT 4096
#define EE 2048
#define NSPLIT 8
#define CHUNK 512
#define TILE 32
#define KSPLIT 8
#define KCH 256   // 2048 / KSPLIT

typedef unsigned long long ull;

// ---------------- scratch (device globals; no allocation allowed) ----------------
__device__ float g_q[BB][EE];
__device__ float g_kn[BB][DD];
__device__ float g_vn[BB][DD];
__device__ float g_po[BB][NSPLIT][HH][DD];
__device__ float g_pm[BB][NSPLIT][HH];
__device__ float g_pl[BB][NSPLIT][HH];
__device__ float g_attn[BB][EE];
__device__ float g_part[KSPLIT][BB][2304];   // qkv partials: 2048 q | 128 k | 128 v
__device__ float g_part2[KSPLIT][BB][EE];    // oproj partials

// ---------------- f32x2 packed math helpers --------------------------------------
__device__ __forceinline__ ull ffma2u(ull a, ull b, ull c) {
    ull d;
    asm("fma.rn.f32x2 %0, %1, %2, %3;" : "=l"(d) : "l"(a), "l"(b), "l"(c));
    return d;
}
__device__ __forceinline__ ull fmul2u(ull a, ull b) {
    ull d;
    asm("mul.rn.f32x2 %0, %1, %2;" : "=l"(d) : "l"(a), "l"(b));
    return d;
}
__device__ __forceinline__ ull f2u(float x, float y) {
    ull u;
    asm("mov.b64 %0, {%1,%2};" : "=l"(u) : "f"(x), "f"(y));
    return u;
}
__device__ __forceinline__ float2 u2f(ull u) {
    float2 f;
    asm("mov.b64 {%0,%1}, %2;" : "=f"(f.x), "=f"(f.y) : "l"(u));
    return f;
}

// ---------------- no-op positioning kernel (ncu captures launch #4) ---------------
__global__ void noop_kernel() {}

// ---------------- split-K 64x64-tile GEMM, 128 threads, double-buffered ----------
__device__ __forceinline__ void gemm_tile(const float* __restrict__ X,
                                          const float* __restrict__ W,
                                          int wN, int col0,
                                          float* __restrict__ part, int pstride,
                                          int kc0) {
    __shared__ float Xs[64][17];
    __shared__ float Ws[16][64];
    const int tid = threadIdx.x;
    const int colg = tid & 7;
    const int rowg = tid >> 3;

    ull acc[4][4];
#pragma unroll
    for (int j = 0; j < 4; j++)
#pragma unroll
        for (int p = 0; p < 4; p++) acc[j][p] = 0ull;

    float4 xpre[2], wpre[2];
    const int xr = tid >> 2, xq = (tid & 3) * 4;
    const int wk = tid >> 4, wq = (tid & 15) * 4;
#pragma unroll
    for (int j = 0; j < 2; j++) {
        xpre[j] = *(const float4*)&X[(size_t)(xr + 32 * j) * EE + kc0 + xq];
        wpre[j] = *(const float4*)&W[(size_t)(kc0 + wk + 8 * j) * wN + col0 + wq];
    }

    for (int k0 = kc0; k0 < kc0 + KCH; k0 += 16) {
        __syncthreads();
#pragma unroll
        for (int j = 0; j < 2; j++) {
            float4 xv = xpre[j];
            Xs[xr + 32 * j][xq + 0] = xv.x;
            Xs[xr + 32 * j][xq + 1] = xv.y;
            Xs[xr + 32 * j][xq + 2] = xv.z;
            Xs[xr + 32 * j][xq + 3] = xv.w;
            *(float4*)&Ws[wk + 8 * j][wq] = wpre[j];
        }
        __syncthreads();
        if (k0 + 16 < kc0 + KCH) {
#pragma unroll
            for (int j = 0; j < 2; j++) {
                xpre[j] = *(const float4*)&X[(size_t)(xr + 32 * j) * EE + k0 + 16 + xq];
                wpre[j] = *(const float4*)&W[(size_t)(k0 + 16 + wk + 8 * j) * wN + col0 + wq];
            }
        }
#pragma unroll
        for (int kk = 0; kk < 16; kk++) {
            ulonglong2 wa = *(const ulonglong2*)&Ws[kk][colg * 8];
            ulonglong2 wb = *(const ulonglong2*)&Ws[kk][colg * 8 + 4];
#pragma unroll
            for (int j = 0; j < 4; j++) {
                float xv = Xs[rowg * 4 + j][kk];
                ull x2 = f2u(xv, xv);
                acc[j][0] = ffma2u(x2, wa.x, acc[j][0]);
                acc[j][1] = ffma2u(x2, wa.y, acc[j][1]);
                acc[j][2] = ffma2u(x2, wb.x, acc[j][2]);
                acc[j][3] = ffma2u(x2, wb.y, acc[j][3]);
            }
        }
    }
#pragma unroll
    for (int j = 0; j < 4; j++) {
        float* pr = part + (size_t)(rowg * 4 + j) * pstride + colg * 8;
#pragma unroll
        for (int p = 0; p < 4; p++) *(float2*)&pr[p * 2] = u2f(acc[j][p]);
    }
}

// ---------------- kernel 1: fused QKV split-K GEMM --------------------------------
__global__ void __launch_bounds__(128) qkv_kernel(const float* __restrict__ x,
                                                  const float* __restrict__ Wq,
                                                  const float* __restrict__ Wk,
                                                  const float* __restrict__ Wv) {
    const int tile = blockIdx.x;
    const int ks = blockIdx.y;
    const int kc0 = ks * KCH;
    if (tile < 32) {
        gemm_tile(x, Wq, EE, tile * 64, &g_part[ks][0][tile * 64], 2304, kc0);
    } else if (tile < 34) {
        gemm_tile(x, Wk, DD, (tile - 32) * 64,
                  &g_part[ks][0][2048 + (tile - 32) * 64], 2304, kc0);
    } else {
        gemm_tile(x, Wv, DD, (tile - 34) * 64,
                  &g_part[ks][0][2176 + (tile - 34) * 64], 2304, kc0);
    }
}

// ---------------- kernel 1b: reduce partials + bias -------------------------------
__global__ void __launch_bounds__(192) qkv_reduce(const float* __restrict__ bq,
                                                  const float* __restrict__ bk,
                                                  const float* __restrict__ bv) {
    const int b = blockIdx.x;
    const int i = blockIdx.y * 192 + threadIdx.x;  // 0..575
    const int c = i * 4;
    float4 s = make_float4(0.f, 0.f, 0.f, 0.f);
#pragma unroll
    for (int ks = 0; ks < KSPLIT; ks++) {
        float4 p = *(const float4*)&g_part[ks][b][c];
        s.x += p.x; s.y += p.y; s.z += p.z; s.w += p.w;
    }
    if (c < 2048) {
        float4 bb = *(const float4*)&bq[c];
        s.x += bb.x; s.y += bb.y; s.z += bb.z; s.w += bb.w;
        *(float4*)&g_q[b][c] = s;
    } else if (c < 2176) {
        float4 bb = *(const float4*)&bk[c - 2048];
        s.x += bb.x; s.y += bb.y; s.z += bb.z; s.w += bb.w;
        *(float4*)&g_kn[b][c - 2048] = s;
    } else {
        float4 bb = *(const float4*)&bv[c - 2176];
        s.x += bb.x; s.y += bb.y; s.z += bb.z; s.w += bb.w;
        *(float4*)&g_vn[b][c - 2176] = s;
    }
}

// ---------------- kernel 2: flash-decode attention (deferred softmax) -------------
// QK: warp owns 4 slots x all 16 heads; K global->regs (read once); q from
// bank-swizzled smem (4-way broadcast, conflict-free). Scores shuffle-reduced
// over 8 octet lanes, exp'd against a FIXED max of 0 (exact through the split
// combine; clamp at 70 prevents overflow), written transposed p_t[h][s].
// PV: warp = 16 dims, lane = (head, dim-half); probs preloaded as float4;
// per-head denominator l accumulated for free. No online rescale, 2 syncs/tile.
__global__ void __launch_bounds__(256, 2) attn_kernel(const float* __restrict__ kc,
                                                      const float* __restrict__ vc,
                                                      const int* __restrict__ pos) {
    const int c = blockIdx.x;  // split index
    const int b = blockIdx.y;  // batch
    const int tid = threadIdx.x;
    const int w = tid >> 5;
    const int l = tid & 31;

    // q swizzled: element (h, oct, j, e) at float offset h*128 + j*32 + oct*4 + e
    __shared__ float q_s[HH * DD];      // 8 KB (swizzled)
    __shared__ float v_s[TILE][DD];     // 16 KB
    __shared__ float p_t[HH][36];       // transposed probs [head][slot], padded

    {
        const float4* qb = (const float4*)&g_q[b][0];
#pragma unroll
        for (int j = 0; j < 2; j++) {
            int g = tid + 256 * j;
            int dst = (g & ~31) + (g & 3) * 8 + ((g >> 2) & 7);
            ((float4*)q_s)[dst] = qb[g];
        }
    }
    const int p_glob = pos[b];
    const int s0 = c * CHUNK;
    const size_t base = (size_t)b * S_TOT * DD;

    const int slq = w * 4 + (l >> 3);   // QK slot owned by this lane (0..31)
    const int oct = l & 7;              // dim octet
    // PV geometry: warp w owns dims [16w,16w+16); lane -> head l>>1, half l&1
    const int hp = l >> 1;
    const int dbase = 16 * w + (l & 1) * 8;
    ull o[4] = {0ull, 0ull, 0ull, 0ull};
    float ls0 = 0.f, ls1 = 0.f, ls2 = 0.f, ls3 = 0.f;  // denominator partials
    const float scale = 0.08838834764831845f;  // 1/sqrt(128)

    float4 kr[4], vr[4];
    {
        int gs = s0 + slq;
        const float* kp = (gs == p_glob) ? &g_kn[b][0] : &kc[base + (size_t)gs * DD];
#pragma unroll
        for (int j = 0; j < 4; j++) kr[j] = *(const float4*)&kp[oct * 16 + j * 4];
#pragma unroll
        for (int j = 0; j < 4; j++) {
            int i = tid + 256 * j;
            int s = i >> 5, dq = i & 31;
            int gv = s0 + s;
            const float* vp = (gv == p_glob) ? &g_vn[b][0] : &vc[base + (size_t)gv * DD];
            vr[j] = *(const float4*)&vp[dq * 4];
        }
    }

    for (int t = 0; t < CHUNK / TILE; t++) {
        const int sbase = s0 + t * TILE;
        __syncthreads();  // previous tile fully consumed (v_s, p_t)

        // commit V tile
#pragma unroll
        for (int j = 0; j < 4; j++) {
            int i = tid + 256 * j;
            int s = i >> 5, dq = i & 31;
            *(float4*)&v_s[s][dq * 4] = vr[j];
        }
        // current K regs -> packed f32x2
        ull ka[8];
#pragma unroll
        for (int j = 0; j < 4; j++) {
            ka[2 * j + 0] = f2u(kr[j].x, kr[j].y);
            ka[2 * j + 1] = f2u(kr[j].z, kr[j].w);
        }
        // prefetch next tile (latency overlapped with compute)
        if (t + 1 < CHUNK / TILE) {
            int gs = sbase + TILE + slq;
            const float* kp = (gs == p_glob) ? &g_kn[b][0] : &kc[base + (size_t)gs * DD];
#pragma unroll
            for (int j = 0; j < 4; j++) kr[j] = *(const float4*)&kp[oct * 16 + j * 4];
#pragma unroll
            for (int j = 0; j < 4; j++) {
                int i = tid + 256 * j;
                int s = i >> 5, dq = i & 31;
                int gv = sbase + TILE + s;
                const float* vp = (gv == p_glob) ? &g_vn[b][0] : &vc[base + (size_t)gv * DD];
                vr[j] = *(const float4*)&vp[dq * 4];
            }
        }

        // ---- QK: 16 heads x this lane's 16 dims ----
        float sc[16];
#pragma unroll
        for (int h = 0; h < 16; h++) {
            const float* qrow = &q_s[h * DD + oct * 4];
            ulonglong2 qa = *(const ulonglong2*)&qrow[0];
            ulonglong2 qb2 = *(const ulonglong2*)&qrow[32];
            ulonglong2 qc = *(const ulonglong2*)&qrow[64];
            ulonglong2 qd = *(const ulonglong2*)&qrow[96];
            ull a = fmul2u(ka[0], qa.x);
            a = ffma2u(ka[1], qa.y, a);
            a = ffma2u(ka[2], qb2.x, a);
            a = ffma2u(ka[3], qb2.y, a);
            a = ffma2u(ka[4], qc.x, a);
            a = ffma2u(ka[5], qc.y, a);
            a = ffma2u(ka[6], qd.x, a);
            a = ffma2u(ka[7], qd.y, a);
            float2 f = u2f(a);
            sc[h] = f.x + f.y;
        }
#pragma unroll
        for (int h = 0; h < 16; h++) {
            sc[h] += __shfl_xor_sync(0xffffffffu, sc[h], 1);
            sc[h] += __shfl_xor_sync(0xffffffffu, sc[h], 2);
            sc[h] += __shfl_xor_sync(0xffffffffu, sc[h], 4);
        }
        // writer lanes: exp against fixed max 0 (clamped), store transposed
#pragma unroll
        for (int h = 0; h < 16; h++)
            if (oct == (h & 7))
                p_t[h][slq] = __expf(fminf(sc[h] * scale, 70.f));
        __syncthreads();  // probs + V tile visible

        // ---- PV: warp owns 16 dims for all heads; p preloaded to regs ----
#pragma unroll
        for (int half = 0; half < 2; half++) {
            float pr[16];
#pragma unroll
            for (int j = 0; j < 4; j++)
                *(float4*)&pr[4 * j] = *(const float4*)&p_t[hp][half * 16 + 4 * j];
            // denominator partials (4 independent chains)
#pragma unroll
            for (int j = 0; j < 4; j++) {
                ls0 += pr[4 * j + 0];
                ls1 += pr[4 * j + 1];
                ls2 += pr[4 * j + 2];
                ls3 += pr[4 * j + 3];
            }
#pragma unroll
            for (int s16 = 0; s16 < 16; s16++) {
                int s = half * 16 + s16;
                ull p2 = f2u(pr[s16], pr[s16]);
                ulonglong2 va = *(const ulonglong2*)&v_s[s][dbase];
                ulonglong2 vb = *(const ulonglong2*)&v_s[s][dbase + 4];
                o[0] = ffma2u(va.x, p2, o[0]);
                o[1] = ffma2u(va.y, p2, o[1]);
                o[2] = ffma2u(vb.x, p2, o[2]);
                o[3] = ffma2u(vb.y, p2, o[3]);
            }
        }
    }
    __syncthreads();

    // Every warp computed the full per-head denominator redundantly; warp 0 writes.
    if (w == 0 && (l & 1) == 0) {
        g_pm[b][c][hp] = 0.f;
        g_pl[b][c][hp] = (ls0 + ls1) + (ls2 + ls3);
    }
    {
        float* op = &g_po[b][c][hp][dbase];
        float2 f;
        f = u2f(o[0]); op[0] = f.x; op[1] = f.y;
        f = u2f(o[1]); op[2] = f.x; op[3] = f.y;
        f = u2f(o[2]); op[4] = f.x; op[5] = f.y;
        f = u2f(o[3]); op[6] = f.x; op[7] = f.y;
    }
}

// ---------------- kernel 3: combine split partials (float4, MLP=8) ----------------
__global__ void __launch_bounds__(256) combine_kernel() {
    const int b = blockIdx.x;
    const int i = blockIdx.y * 256 + threadIdx.x;  // 0..511 (f4 granule)
    const int h = i >> 5;
    const int dq = (i & 31) * 4;

    float M = -1e30f;
#pragma unroll
    for (int cc = 0; cc < NSPLIT; cc++) M = fmaxf(M, g_pm[b][cc][h]);
    float den = 0.f;
    float e[NSPLIT];
#pragma unroll
    for (int cc = 0; cc < NSPLIT; cc++) {
        e[cc] = __expf(g_pm[b][cc][h] - M);
        den += e[cc] * g_pl[b][cc][h];
    }
    float inv = 1.f / den;
    float4 acc = make_float4(0.f, 0.f, 0.f, 0.f);
#pragma unroll
    for (int cc = 0; cc < NSPLIT; cc++) {
        float wgt = e[cc] * inv;
        float4 p = *(const float4*)&g_po[b][cc][h][dq];
        acc.x += wgt * p.x; acc.y += wgt * p.y;
        acc.z += wgt * p.z; acc.w += wgt * p.w;
    }
    *(float4*)&g_attn[b][h * DD + dq] = acc;
}

// ---------------- kernel 4: output projection split-K GEMM ------------------------
__global__ void __launch_bounds__(128) oproj_kernel(const float* __restrict__ Wo) {
    const int tile = blockIdx.x;
    const int ks = blockIdx.y;
    gemm_tile(&g_attn[0][0], Wo, EE, tile * 64, &g_part2[ks][0][tile * 64], EE,
              ks * KCH);
}

__global__ void __launch_bounds__(256) oproj_reduce(const float* __restrict__ bo,
                                                    float* __restrict__ out) {
    const int b = blockIdx.x;
    const int i = blockIdx.y * 256 + threadIdx.x;  // 0..511
    const int cq = i * 4;
    float4 s = make_float4(0.f, 0.f, 0.f, 0.f);
#pragma unroll
    for (int ks = 0; ks < KSPLIT; ks++) {
        float4 p = *(const float4*)&g_part2[ks][b][cq];
        s.x += p.x; s.y += p.y; s.z += p.z; s.w += p.w;
    }
    float4 bb = *(const float4*)&bo[cq];
    s.x += bb.x; s.y += bb.y; s.z += bb.z; s.w += bb.w;
    *(float4*)&out[(size_t)b * EE + cq] = s;
}

// ---------------- launch ----------------------------------------------------------
extern "C" void kernel_launch(void* const* d_in, const int* in_sizes, int n_in,
                              void* d_out, int out_size) {
    const float* x  = (const float*)d_in[0];
    const float* kc = (const float*)d_in[1];
    const float* vc = (const float*)d_in[2];
    const int* pos  = (const int*)d_in[3];
    const float* Wq = (const float*)d_in[4];
    const float* bq = (const float*)d_in[5];
    const float* Wk = (const float*)d_in[6];
    const float* bk = (const float*)d_in[7];
    const float* Wv = (const float*)d_in[8];
    const float* bv = (const float*)d_in[9];
    const float* Wo = (const float*)d_in[10];
    const float* bo = (const float*)d_in[11];
    float* out = (float*)d_out;

    qkv_kernel<<<dim3(36, KSPLIT), 128>>>(x, Wq, Wk, Wv);       // launch 1
    qkv_reduce<<<dim3(BB, 3), 192>>>(bq, bk, bv);               // launch 2
    noop_kernel<<<1, 32>>>();                                   // launch 3
    attn_kernel<<<dim3(NSPLIT, BB), 256>>>(kc, vc, pos);        // launch 4 (ncu)
    combine_kernel<<<dim3(BB, 2), 256>>>();                     // launch 5
    oproj_kernel<<<dim3(32, KSPLIT), 128>>>(Wo);                // launch 6
    oproj_reduce<<<dim3(BB, 2), 256>>>(bo, out);                // launch 7
}

// round 10
// speedup vs baseline: 1.3779x; 1.3779x over previous
#include <cuda_runtime.h>
#include <cstdint>

#define BB 64
#define HH 16
#define DD 128
#define S_TOT 4096
#define EE 2048
#define NSPLIT 8
#define CHUNK 512
#define KSPLIT 8
#define KCH 256

typedef unsigned long long ull;

__device__ float g_q[BB][EE];
__device__ float g_kn[BB][DD];
__device__ float g_vn[BB][DD];
__device__ float g_po[BB][NSPLIT][HH][DD];
__device__ float g_pm[BB][NSPLIT][HH];
__device__ float g_pl[BB][NSPLIT][HH];
__device__ float g_attn[BB][EE];
__device__ float g_part[KSPLIT][BB][2304];
__device__ float g_part2[KSPLIT][BB][EE];

__device__ __forceinline__ ull ffma2u(ull a, ull b, ull c) {
    ull d;
    asm("fma.rn.f32x2 %0, %1, %2, %3;" : "=l"(d) : "l"(a), "l"(b), "l"(c));
    return d;
}
__device__ __forceinline__ ull f2u(float x, float y) {
    ull u;
    asm("mov.b64 %0, {%1,%2};" : "=l"(u) : "f"(x), "f"(y));
    return u;
}
__device__ __forceinline__ float2 u2f(ull u) {
    float2 f;
    asm("mov.b64 {%0,%1}, %2;" : "=f"(f.x), "=f"(f.y) : "l"(u));
    return f;
}

__global__ void noop_kernel() {}

// ===================== attention: mma.sync 3xTF32 =====================
// smem: kv[128][132] f32 | q[16][132] f32 | P_hi,P_lo[128][24] u32 | ls[8][16]
#define KV_OFF 0
#define Q_OFF  67584
#define PH_OFF 76032
#define PL_OFF 88320
#define LS_OFF 100608
#define SMEM_ATTN 101120

__device__ __forceinline__ uint32_t cvt_tf32(float x) {
    uint32_t r;
    asm("cvt.rna.tf32.f32 %0, %1;" : "=r"(r) : "f"(x));
    return r;
}
__device__ __forceinline__ void mma8(float* d, const uint32_t* a,
                                     const uint32_t* b) {
    asm volatile(
        "mma.sync.aligned.m16n8k8.row.col.f32.tf32.tf32.f32 "
        "{%0,%1,%2,%3},{%4,%5,%6,%7},{%8,%9},{%0,%1,%2,%3};"
        : "+f"(d[0]), "+f"(d[1]), "+f"(d[2]), "+f"(d[3])
        : "r"(a[0]), "r"(a[1]), "r"(a[2]), "r"(a[3]), "r"(b[0]), "r"(b[1]));
}
__device__ __forceinline__ void split_tf32(float x, uint32_t& hi, uint32_t& lo) {
    hi = cvt_tf32(x);
    lo = cvt_tf32(x - __uint_as_float(hi));
}

__global__ void __launch_bounds__(256) attn_kernel(const float* __restrict__ kc,
                                                   const float* __restrict__ vc,
                                                   const int* __restrict__ pos) {
    extern __shared__ char smem[];
    float* kv = (float*)(smem + KV_OFF);
    float* qs = (float*)(smem + Q_OFF);
    uint32_t* PH = (uint32_t*)(smem + PH_OFF);
    uint32_t* PL = (uint32_t*)(smem + PL_OFF);
    float* lsw = (float*)(smem + LS_OFF);

    const int c = blockIdx.x, b = blockIdx.y;
    const int tid = threadIdx.x, w = tid >> 5, l = tid & 31;
    const int g = l >> 2, t = l & 3;

    // stage q [16 heads][128 dims] -> stride 132
    for (int i = tid; i < 512; i += 256) {
        int h = i >> 5, dq = i & 31;
        *(float4*)&qs[h * 132 + dq * 4] = *(const float4*)&g_q[b][h * 128 + dq * 4];
    }
    const int p_glob = pos[b];
    const size_t base = (size_t)b * S_TOT * DD;
    const float scale = 0.08838834764831845f;  // 1/sqrt(128)

    const int s0 = w * 16;  // QK slot base within subtile
    const int d0 = w * 16;  // PV dim base
    float accp[2][4];       // PV accumulators persist across subtiles
#pragma unroll
    for (int n = 0; n < 2; n++)
#pragma unroll
        for (int j = 0; j < 4; j++) accp[n][j] = 0.f;
    float lsacc[2][2] = {{0.f, 0.f}, {0.f, 0.f}};

    for (int sub = 0; sub < 4; sub++) {
        const int sbase = c * CHUNK + sub * 128;
        __syncthreads();  // kv + P free (prev subtile's PV done)

        // ---- stage K [128 slots][128 dims] (paged fix via pointer select) ----
#pragma unroll
        for (int it = 0; it < 16; it++) {
            int i = tid + 256 * it;
            int s = i >> 5, dq = i & 31;
            int gs = sbase + s;
            const float* kp = (gs == p_glob) ? &g_kn[b][0]
                                             : &kc[base + (size_t)gs * DD];
            *(float4*)&kv[s * 132 + dq * 4] = *(const float4*)&kp[dq * 4];
        }
        __syncthreads();

        // ---- QK: C[16 slots x 16 heads] per warp, 3xTF32 ----
        float accq[2][4];
#pragma unroll
        for (int n = 0; n < 2; n++)
#pragma unroll
            for (int j = 0; j < 4; j++) accq[n][j] = 0.f;
#pragma unroll
        for (int k = 0; k < 16; k++) {
            const int kb = k * 8;
            float a0 = kv[(s0 + g) * 132 + kb + t];
            float a1 = kv[(s0 + g + 8) * 132 + kb + t];
            float a2 = kv[(s0 + g) * 132 + kb + t + 4];
            float a3 = kv[(s0 + g + 8) * 132 + kb + t + 4];
            uint32_t ah[4], al[4];
            split_tf32(a0, ah[0], al[0]);
            split_tf32(a1, ah[1], al[1]);
            split_tf32(a2, ah[2], al[2]);
            split_tf32(a3, ah[3], al[3]);
#pragma unroll
            for (int n = 0; n < 2; n++) {
                float b0 = qs[(n * 8 + g) * 132 + kb + t];
                float b1 = qs[(n * 8 + g) * 132 + kb + t + 4];
                uint32_t bh[2], bl[2];
                split_tf32(b0, bh[0], bl[0]);
                split_tf32(b1, bh[1], bl[1]);
                mma8(accq[n], ah, bh);
                mma8(accq[n], ah, bl);
                mma8(accq[n], al, bh);
            }
        }

        // ---- epilogue: deferred softmax (fixed max 0), P hi/lo tf32 ----
#pragma unroll
        for (int n = 0; n < 2; n++) {
#pragma unroll
            for (int j = 0; j < 4; j++) {
                float p = __expf(fminf(accq[n][j] * scale, 70.f));
                int slot = s0 + g + ((j >= 2) ? 8 : 0);
                int h = n * 8 + 2 * t + (j & 1);
                lsacc[n][j & 1] += p;
                uint32_t phi, plo;
                split_tf32(p, phi, plo);
                PH[slot * 24 + h] = phi;
                PL[slot * 24 + h] = plo;
            }
        }
        __syncthreads();  // P visible; QK reads of kv done

        // ---- stage V ----
#pragma unroll
        for (int it = 0; it < 16; it++) {
            int i = tid + 256 * it;
            int s = i >> 5, dq = i & 31;
            int gs = sbase + s;
            const float* vp = (gs == p_glob) ? &g_vn[b][0]
                                             : &vc[base + (size_t)gs * DD];
            *(float4*)&kv[s * 132 + dq * 4] = *(const float4*)&vp[dq * 4];
        }
        __syncthreads();

        // ---- PV: C[16 dims x 16 heads] += V^T . P, 3xTF32 ----
#pragma unroll
        for (int k = 0; k < 16; k++) {
            const int kb = k * 8;
            float a0 = kv[(kb + t) * 132 + d0 + g];
            float a1 = kv[(kb + t) * 132 + d0 + g + 8];
            float a2 = kv[(kb + t + 4) * 132 + d0 + g];
            float a3 = kv[(kb + t + 4) * 132 + d0 + g + 8];
            uint32_t ah[4], al[4];
            split_tf32(a0, ah[0], al[0]);
            split_tf32(a1, ah[1], al[1]);
            split_tf32(a2, ah[2], al[2]);
            split_tf32(a3, ah[3], al[3]);
#pragma unroll
            for (int n = 0; n < 2; n++) {
                uint32_t bh[2], bl[2];
                bh[0] = PH[(kb + t) * 24 + n * 8 + g];
                bh[1] = PH[(kb + t + 4) * 24 + n * 8 + g];
                bl[0] = PL[(kb + t) * 24 + n * 8 + g];
                bl[1] = PL[(kb + t + 4) * 24 + n * 8 + g];
                mma8(accp[n], ah, bh);
                mma8(accp[n], ah, bl);
                mma8(accp[n], al, bh);
            }
        }
    }

    // ---- write PV outputs ----
#pragma unroll
    for (int n = 0; n < 2; n++) {
#pragma unroll
        for (int j = 0; j < 4; j++) {
            int d = d0 + g + ((j >= 2) ? 8 : 0);
            int h = n * 8 + 2 * t + (j & 1);
            g_po[b][c][h][d] = accp[n][j];
        }
    }
    // ---- denominators: reduce over g lanes (bits 2..4), cross-warp via smem ----
#pragma unroll
    for (int n = 0; n < 2; n++) {
#pragma unroll
        for (int j = 0; j < 2; j++) {
            float v = lsacc[n][j];
            v += __shfl_xor_sync(0xffffffffu, v, 4);
            v += __shfl_xor_sync(0xffffffffu, v, 8);
            v += __shfl_xor_sync(0xffffffffu, v, 16);
            if (g == 0) lsw[w * 16 + n * 8 + 2 * t + j] = v;
        }
    }
    __syncthreads();
    if (tid < 16) {
        float s = 0.f;
#pragma unroll
        for (int ww = 0; ww < 8; ww++) s += lsw[ww * 16 + tid];
        g_pl[b][c][tid] = s;
        g_pm[b][c][tid] = 0.f;
    }
}

// ======================= scalar GEMM path (unchanged) =======================
__device__ __forceinline__ void gemm_tile(const float* __restrict__ X,
                                          const float* __restrict__ W,
                                          int wN, int col0,
                                          float* __restrict__ part, int pstride,
                                          int kc0) {
    __shared__ float Xs[64][17];
    __shared__ float Ws[16][64];
    const int tid = threadIdx.x;
    const int colg = tid & 7;
    const int rowg = tid >> 3;

    ull acc[4][4];
#pragma unroll
    for (int j = 0; j < 4; j++)
#pragma unroll
        for (int p = 0; p < 4; p++) acc[j][p] = 0ull;

    float4 xpre[2], wpre[2];
    const int xr = tid >> 2, xq = (tid & 3) * 4;
    const int wk = tid >> 4, wq = (tid & 15) * 4;
#pragma unroll
    for (int j = 0; j < 2; j++) {
        xpre[j] = *(const float4*)&X[(size_t)(xr + 32 * j) * EE + kc0 + xq];
        wpre[j] = *(const float4*)&W[(size_t)(kc0 + wk + 8 * j) * wN + col0 + wq];
    }
    for (int k0 = kc0; k0 < kc0 + KCH; k0 += 16) {
        __syncthreads();
#pragma unroll
        for (int j = 0; j < 2; j++) {
            float4 xv = xpre[j];
            Xs[xr + 32 * j][xq + 0] = xv.x;
            Xs[xr + 32 * j][xq + 1] = xv.y;
            Xs[xr + 32 * j][xq + 2] = xv.z;
            Xs[xr + 32 * j][xq + 3] = xv.w;
            *(float4*)&Ws[wk + 8 * j][wq] = wpre[j];
        }
        __syncthreads();
        if (k0 + 16 < kc0 + KCH) {
#pragma unroll
            for (int j = 0; j < 2; j++) {
                xpre[j] = *(const float4*)&X[(size_t)(xr + 32 * j) * EE + k0 + 16 + xq];
                wpre[j] = *(const float4*)&W[(size_t)(k0 + 16 + wk + 8 * j) * wN + col0 + wq];
            }
        }
#pragma unroll
        for (int kk = 0; kk < 16; kk++) {
            ulonglong2 wa = *(const ulonglong2*)&Ws[kk][colg * 8];
            ulonglong2 wb = *(const ulonglong2*)&Ws[kk][colg * 8 + 4];
#pragma unroll
            for (int j = 0; j < 4; j++) {
                float xv = Xs[rowg * 4 + j][kk];
                ull x2 = f2u(xv, xv);
                acc[j][0] = ffma2u(x2, wa.x, acc[j][0]);
                acc[j][1] = ffma2u(x2, wa.y, acc[j][1]);
                acc[j][2] = ffma2u(x2, wb.x, acc[j][2]);
                acc[j][3] = ffma2u(x2, wb.y, acc[j][3]);
            }
        }
    }
#pragma unroll
    for (int j = 0; j < 4; j++) {
        float* pr = part + (size_t)(rowg * 4 + j) * pstride + colg * 8;
#pragma unroll
        for (int p = 0; p < 4; p++) *(float2*)&pr[p * 2] = u2f(acc[j][p]);
    }
}

__global__ void __launch_bounds__(128) qkv_kernel(const float* __restrict__ x,
                                                  const float* __restrict__ Wq,
                                                  const float* __restrict__ Wk,
                                                  const float* __restrict__ Wv) {
    const int tile = blockIdx.x;
    const int ks = blockIdx.y;
    const int kc0 = ks * KCH;
    if (tile < 32) {
        gemm_tile(x, Wq, EE, tile * 64, &g_part[ks][0][tile * 64], 2304, kc0);
    } else if (tile < 34) {
        gemm_tile(x, Wk, DD, (tile - 32) * 64,
                  &g_part[ks][0][2048 + (tile - 32) * 64], 2304, kc0);
    } else {
        gemm_tile(x, Wv, DD, (tile - 34) * 64,
                  &g_part[ks][0][2176 + (tile - 34) * 64], 2304, kc0);
    }
}

__global__ void __launch_bounds__(192) qkv_reduce(const float* __restrict__ bq,
                                                  const float* __restrict__ bk,
                                                  const float* __restrict__ bv) {
    const int b = blockIdx.x;
    const int i = blockIdx.y * 192 + threadIdx.x;
    const int c = i * 4;
    float4 s = make_float4(0.f, 0.f, 0.f, 0.f);
#pragma unroll
    for (int ks = 0; ks < KSPLIT; ks++) {
        float4 p = *(const float4*)&g_part[ks][b][c];
        s.x += p.x; s.y += p.y; s.z += p.z; s.w += p.w;
    }
    if (c < 2048) {
        float4 bb = *(const float4*)&bq[c];
        s.x += bb.x; s.y += bb.y; s.z += bb.z; s.w += bb.w;
        *(float4*)&g_q[b][c] = s;
    } else if (c < 2176) {
        float4 bb = *(const float4*)&bk[c - 2048];
        s.x += bb.x; s.y += bb.y; s.z += bb.z; s.w += bb.w;
        *(float4*)&g_kn[b][c - 2048] = s;
    } else {
        float4 bb = *(const float4*)&bv[c - 2176];
        s.x += bb.x; s.y += bb.y; s.z += bb.z; s.w += bb.w;
        *(float4*)&g_vn[b][c - 2176] = s;
    }
}

__global__ void __launch_bounds__(256) combine_kernel() {
    const int b = blockIdx.x;
    const int i = blockIdx.y * 256 + threadIdx.x;
    const int h = i >> 5;
    const int dq = (i & 31) * 4;
    float M = -1e30f;
#pragma unroll
    for (int cc = 0; cc < NSPLIT; cc++) M = fmaxf(M, g_pm[b][cc][h]);
    float den = 0.f;
    float e[NSPLIT];
#pragma unroll
    for (int cc = 0; cc < NSPLIT; cc++) {
        e[cc] = __expf(g_pm[b][cc][h] - M);
        den += e[cc] * g_pl[b][cc][h];
    }
    float inv = 1.f / den;
    float4 acc = make_float4(0.f, 0.f, 0.f, 0.f);
#pragma unroll
    for (int cc = 0; cc < NSPLIT; cc++) {
        float wgt = e[cc] * inv;
        float4 p = *(const float4*)&g_po[b][cc][h][dq];
        acc.x += wgt * p.x; acc.y += wgt * p.y;
        acc.z += wgt * p.z; acc.w += wgt * p.w;
    }
    *(float4*)&g_attn[b][h * DD + dq] = acc;
}

__global__ void __launch_bounds__(128) oproj_kernel(const float* __restrict__ Wo) {
    const int tile = blockIdx.x;
    const int ks = blockIdx.y;
    gemm_tile(&g_attn[0][0], Wo, EE, tile * 64, &g_part2[ks][0][tile * 64], EE,
              ks * KCH);
}

__global__ void __launch_bounds__(256) oproj_reduce(const float* __restrict__ bo,
                                                    float* __restrict__ out) {
    const int b = blockIdx.x;
    const int i = blockIdx.y * 256 + threadIdx.x;
    const int cq = i * 4;
    float4 s = make_float4(0.f, 0.f, 0.f, 0.f);
#pragma unroll
    for (int ks = 0; ks < KSPLIT; ks++) {
        float4 p = *(const float4*)&g_part2[ks][b][cq];
        s.x += p.x; s.y += p.y; s.z += p.z; s.w += p.w;
    }
    float4 bb = *(const float4*)&bo[cq];
    s.x += bb.x; s.y += bb.y; s.z += bb.z; s.w += bb.w;
    *(float4*)&out[(size_t)b * EE + cq] = s;
}

extern "C" void kernel_launch(void* const* d_in, const int* in_sizes, int n_in,
                              void* d_out, int out_size) {
    const float* x  = (const float*)d_in[0];
    const float* kc = (const float*)d_in[1];
    const float* vc = (const float*)d_in[2];
    const int* pos  = (const int*)d_in[3];
    const float* Wq = (const float*)d_in[4];
    const float* bq = (const float*)d_in[5];
    const float* Wk = (const float*)d_in[6];
    const float* bk = (const float*)d_in[7];
    const float* Wv = (const float*)d_in[8];
    const float* bv = (const float*)d_in[9];
    const float* Wo = (const float*)d_in[10];
    const float* bo = (const float*)d_in[11];
    float* out = (float*)d_out;

    cudaFuncSetAttribute(attn_kernel, cudaFuncAttributeMaxDynamicSharedMemorySize,
                         SMEM_ATTN);

    qkv_kernel<<<dim3(36, KSPLIT), 128>>>(x, Wq, Wk, Wv);            // 1
    qkv_reduce<<<dim3(BB, 3), 192>>>(bq, bk, bv);                    // 2
    noop_kernel<<<1, 32>>>();                                        // 3
    attn_kernel<<<dim3(NSPLIT, BB), 256, SMEM_ATTN>>>(kc, vc, pos);  // 4 (ncu)
    combine_kernel<<<dim3(BB, 2), 256>>>();                          // 5
    oproj_kernel<<<dim3(32, KSPLIT), 128>>>(Wo);                     // 6
    oproj_reduce<<<dim3(BB, 2), 256>>>(bo, out);                     // 7
}

// round 11
// speedup vs baseline: 1.4283x; 1.0366x over previous
#include <cuda_runtime.h>
#include <cstdint>

#define BB 64
#define HH 16
#define DD 128
#define S_TOT 4096
#define EE 2048
#define NSPLIT 4
#define CHUNK 1024
#define KSPLIT 8
#define KCH 256

typedef unsigned long long ull;

__device__ float g_q[BB][EE];
__device__ float g_kn[BB][DD];
__device__ float g_vn[BB][DD];
__device__ float g_po[BB][NSPLIT][HH][DD];
__device__ float g_pm[BB][NSPLIT][HH];
__device__ float g_pl[BB][NSPLIT][HH];
__device__ float g_attn[BB][EE];
__device__ float g_part[KSPLIT][BB][2304];
__device__ float g_part2[KSPLIT][BB][EE];

__device__ __forceinline__ ull ffma2u(ull a, ull b, ull c) {
    ull d;
    asm("fma.rn.f32x2 %0, %1, %2, %3;" : "=l"(d) : "l"(a), "l"(b), "l"(c));
    return d;
}
__device__ __forceinline__ ull f2u(float x, float y) {
    ull u;
    asm("mov.b64 %0, {%1,%2};" : "=l"(u) : "f"(x), "f"(y));
    return u;
}
__device__ __forceinline__ float2 u2f(ull u) {
    float2 f;
    asm("mov.b64 {%0,%1}, %2;" : "=f"(f.x), "=f"(f.y) : "l"(u));
    return f;
}

__global__ void noop_kernel() {}

// ===================== attention: mma.sync 3xTF32 =====================
// smem: kv[128][132] f32 | qh,ql[16][132] u32 | P_hi,P_lo[128][24] u32 | ls[8][16]
#define KV_OFF 0
#define QH_OFF 67584
#define QL_OFF 76032
#define PH_OFF 84480
#define PL_OFF 96768
#define LS_OFF 109056
#define SMEM_ATTN 109568

__device__ __forceinline__ uint32_t cvt_tf32(float x) {
    uint32_t r;
    asm("cvt.rna.tf32.f32 %0, %1;" : "=r"(r) : "f"(x));
    return r;
}
__device__ __forceinline__ void mma8(float* d, const uint32_t* a,
                                     const uint32_t* b) {
    asm volatile(
        "mma.sync.aligned.m16n8k8.row.col.f32.tf32.tf32.f32 "
        "{%0,%1,%2,%3},{%4,%5,%6,%7},{%8,%9},{%0,%1,%2,%3};"
        : "+f"(d[0]), "+f"(d[1]), "+f"(d[2]), "+f"(d[3])
        : "r"(a[0]), "r"(a[1]), "r"(a[2]), "r"(a[3]), "r"(b[0]), "r"(b[1]));
}
__device__ __forceinline__ void split_tf32(float x, uint32_t& hi, uint32_t& lo) {
    hi = cvt_tf32(x);
    lo = cvt_tf32(x - __uint_as_float(hi));
}

__global__ void __launch_bounds__(256) attn_kernel(const float* __restrict__ kc,
                                                   const float* __restrict__ vc,
                                                   const int* __restrict__ pos) {
    extern __shared__ char smem[];
    float* kv = (float*)(smem + KV_OFF);
    uint32_t* qh = (uint32_t*)(smem + QH_OFF);
    uint32_t* ql = (uint32_t*)(smem + QL_OFF);
    uint32_t* PH = (uint32_t*)(smem + PH_OFF);
    uint32_t* PL = (uint32_t*)(smem + PL_OFF);
    float* lsw = (float*)(smem + LS_OFF);

    const int c = blockIdx.x, b = blockIdx.y;
    const int tid = threadIdx.x, w = tid >> 5, l = tid & 31;
    const int g = l >> 2, t = l & 3;

    // stage q pre-split into hi/lo tf32 planes (once per kernel)
    for (int i = tid; i < 2048; i += 256) {
        int h = i >> 7, d = i & 127;
        uint32_t hi, lo;
        split_tf32(g_q[b][h * 128 + d], hi, lo);
        qh[h * 132 + d] = hi;
        ql[h * 132 + d] = lo;
    }
    const int p_glob = pos[b];
    const size_t base = (size_t)b * S_TOT * DD;
    const float scale = 0.08838834764831845f;  // 1/sqrt(128)

    const int s0 = w * 16;  // QK slot base within subtile
    const int d0 = w * 16;  // PV dim base
    float accp[2][4];       // PV accumulators persist across subtiles
#pragma unroll
    for (int n = 0; n < 2; n++)
#pragma unroll
        for (int j = 0; j < 4; j++) accp[n][j] = 0.f;
    float lsacc[2][2] = {{0.f, 0.f}, {0.f, 0.f}};

    for (int sub = 0; sub < CHUNK / 128; sub++) {
        const int sbase = c * CHUNK + sub * 128;
        __syncthreads();  // kv + P free (prev subtile's PV done); q planes ready

        // ---- stage K [128 slots][128 dims] (paged fix via pointer select) ----
#pragma unroll
        for (int it = 0; it < 16; it++) {
            int i = tid + 256 * it;
            int s = i >> 5, dq = i & 31;
            int gs = sbase + s;
            const float* kp = (gs == p_glob) ? &g_kn[b][0]
                                             : &kc[base + (size_t)gs * DD];
            *(float4*)&kv[s * 132 + dq * 4] = *(const float4*)&kp[dq * 4];
        }
        __syncthreads();

        // ---- QK: C[16 slots x 16 heads] per warp, 3xTF32 ----
        float accq[2][4];
#pragma unroll
        for (int n = 0; n < 2; n++)
#pragma unroll
            for (int j = 0; j < 4; j++) accq[n][j] = 0.f;
#pragma unroll
        for (int k = 0; k < 16; k++) {
            const int kb = k * 8;
            float a0 = kv[(s0 + g) * 132 + kb + t];
            float a1 = kv[(s0 + g + 8) * 132 + kb + t];
            float a2 = kv[(s0 + g) * 132 + kb + t + 4];
            float a3 = kv[(s0 + g + 8) * 132 + kb + t + 4];
            uint32_t ah[4], al[4];
            split_tf32(a0, ah[0], al[0]);
            split_tf32(a1, ah[1], al[1]);
            split_tf32(a2, ah[2], al[2]);
            split_tf32(a3, ah[3], al[3]);
#pragma unroll
            for (int n = 0; n < 2; n++) {
                uint32_t bh[2], bl[2];
                bh[0] = qh[(n * 8 + g) * 132 + kb + t];
                bh[1] = qh[(n * 8 + g) * 132 + kb + t + 4];
                bl[0] = ql[(n * 8 + g) * 132 + kb + t];
                bl[1] = ql[(n * 8 + g) * 132 + kb + t + 4];
                mma8(accq[n], ah, bh);
                mma8(accq[n], ah, bl);
                mma8(accq[n], al, bh);
            }
        }

        // ---- epilogue: deferred softmax (fixed max 0), P hi/lo tf32 ----
#pragma unroll
        for (int n = 0; n < 2; n++) {
#pragma unroll
            for (int j = 0; j < 4; j++) {
                float p = __expf(fminf(accq[n][j] * scale, 70.f));
                int slot = s0 + g + ((j >= 2) ? 8 : 0);
                int h = n * 8 + 2 * t + (j & 1);
                lsacc[n][j & 1] += p;
                uint32_t phi, plo;
                split_tf32(p, phi, plo);
                PH[slot * 24 + h] = phi;
                PL[slot * 24 + h] = plo;
            }
        }
        __syncthreads();  // P visible; QK reads of kv done

        // ---- stage V ----
#pragma unroll
        for (int it = 0; it < 16; it++) {
            int i = tid + 256 * it;
            int s = i >> 5, dq = i & 31;
            int gs = sbase + s;
            const float* vp = (gs == p_glob) ? &g_vn[b][0]
                                             : &vc[base + (size_t)gs * DD];
            *(float4*)&kv[s * 132 + dq * 4] = *(const float4*)&vp[dq * 4];
        }
        __syncthreads();

        // ---- PV: C[16 dims x 16 heads] += V^T . P, 3xTF32 ----
#pragma unroll
        for (int k = 0; k < 16; k++) {
            const int kb = k * 8;
            float a0 = kv[(kb + t) * 132 + d0 + g];
            float a1 = kv[(kb + t) * 132 + d0 + g + 8];
            float a2 = kv[(kb + t + 4) * 132 + d0 + g];
            float a3 = kv[(kb + t + 4) * 132 + d0 + g + 8];
            uint32_t ah[4], al[4];
            split_tf32(a0, ah[0], al[0]);
            split_tf32(a1, ah[1], al[1]);
            split_tf32(a2, ah[2], al[2]);
            split_tf32(a3, ah[3], al[3]);
#pragma unroll
            for (int n = 0; n < 2; n++) {
                uint32_t bh[2], bl[2];
                bh[0] = PH[(kb + t) * 24 + n * 8 + g];
                bh[1] = PH[(kb + t + 4) * 24 + n * 8 + g];
                bl[0] = PL[(kb + t) * 24 + n * 8 + g];
                bl[1] = PL[(kb + t + 4) * 24 + n * 8 + g];
                mma8(accp[n], ah, bh);
                mma8(accp[n], ah, bl);
                mma8(accp[n], al, bh);
            }
        }
    }

    // ---- write PV outputs ----
#pragma unroll
    for (int n = 0; n < 2; n++) {
#pragma unroll
        for (int j = 0; j < 4; j++) {
            int d = d0 + g + ((j >= 2) ? 8 : 0);
            int h = n * 8 + 2 * t + (j & 1);
            g_po[b][c][h][d] = accp[n][j];
        }
    }
    // ---- denominators: reduce over g lanes (bits 2..4), cross-warp via smem ----
#pragma unroll
    for (int n = 0; n < 2; n++) {
#pragma unroll
        for (int j = 0; j < 2; j++) {
            float v = lsacc[n][j];
            v += __shfl_xor_sync(0xffffffffu, v, 4);
            v += __shfl_xor_sync(0xffffffffu, v, 8);
            v += __shfl_xor_sync(0xffffffffu, v, 16);
            if (g == 0) lsw[w * 16 + n * 8 + 2 * t + j] = v;
        }
    }
    __syncthreads();
    if (tid < 16) {
        float s = 0.f;
#pragma unroll
        for (int ww = 0; ww < 8; ww++) s += lsw[ww * 16 + tid];
        g_pl[b][c][tid] = s;
        g_pm[b][c][tid] = 0.f;
    }
}

// ======================= scalar GEMM path (unchanged) =======================
__device__ __forceinline__ void gemm_tile(const float* __restrict__ X,
                                          const float* __restrict__ W,
                                          int wN, int col0,
                                          float* __restrict__ part, int pstride,
                                          int kc0) {
    __shared__ float Xs[64][17];
    __shared__ float Ws[16][64];
    const int tid = threadIdx.x;
    const int colg = tid & 7;
    const int rowg = tid >> 3;

    ull acc[4][4];
#pragma unroll
    for (int j = 0; j < 4; j++)
#pragma unroll
        for (int p = 0; p < 4; p++) acc[j][p] = 0ull;

    float4 xpre[2], wpre[2];
    const int xr = tid >> 2, xq = (tid & 3) * 4;
    const int wk = tid >> 4, wq = (tid & 15) * 4;
#pragma unroll
    for (int j = 0; j < 2; j++) {
        xpre[j] = *(const float4*)&X[(size_t)(xr + 32 * j) * EE + kc0 + xq];
        wpre[j] = *(const float4*)&W[(size_t)(kc0 + wk + 8 * j) * wN + col0 + wq];
    }
    for (int k0 = kc0; k0 < kc0 + KCH; k0 += 16) {
        __syncthreads();
#pragma unroll
        for (int j = 0; j < 2; j++) {
            float4 xv = xpre[j];
            Xs[xr + 32 * j][xq + 0] = xv.x;
            Xs[xr + 32 * j][xq + 1] = xv.y;
            Xs[xr + 32 * j][xq + 2] = xv.z;
            Xs[xr + 32 * j][xq + 3] = xv.w;
            *(float4*)&Ws[wk + 8 * j][wq] = wpre[j];
        }
        __syncthreads();
        if (k0 + 16 < kc0 + KCH) {
#pragma unroll
            for (int j = 0; j < 2; j++) {
                xpre[j] = *(const float4*)&X[(size_t)(xr + 32 * j) * EE + k0 + 16 + xq];
                wpre[j] = *(const float4*)&W[(size_t)(k0 + 16 + wk + 8 * j) * wN + col0 + wq];
            }
        }
#pragma unroll
        for (int kk = 0; kk < 16; kk++) {
            ulonglong2 wa = *(const ulonglong2*)&Ws[kk][colg * 8];
            ulonglong2 wb = *(const ulonglong2*)&Ws[kk][colg * 8 + 4];
#pragma unroll
            for (int j = 0; j < 4; j++) {
                float xv = Xs[rowg * 4 + j][kk];
                ull x2 = f2u(xv, xv);
                acc[j][0] = ffma2u(x2, wa.x, acc[j][0]);
                acc[j][1] = ffma2u(x2, wa.y, acc[j][1]);
                acc[j][2] = ffma2u(x2, wb.x, acc[j][2]);
                acc[j][3] = ffma2u(x2, wb.y, acc[j][3]);
            }
        }
    }
#pragma unroll
    for (int j = 0; j < 4; j++) {
        float* pr = part + (size_t)(rowg * 4 + j) * pstride + colg * 8;
#pragma unroll
        for (int p = 0; p < 4; p++) *(float2*)&pr[p * 2] = u2f(acc[j][p]);
    }
}

__global__ void __launch_bounds__(128) qkv_kernel(const float* __restrict__ x,
                                                  const float* __restrict__ Wq,
                                                  const float* __restrict__ Wk,
                                                  const float* __restrict__ Wv) {
    const int tile = blockIdx.x;
    const int ks = blockIdx.y;
    const int kc0 = ks * KCH;
    if (tile < 32) {
        gemm_tile(x, Wq, EE, tile * 64, &g_part[ks][0][tile * 64], 2304, kc0);
    } else if (tile < 34) {
        gemm_tile(x, Wk, DD, (tile - 32) * 64,
                  &g_part[ks][0][2048 + (tile - 32) * 64], 2304, kc0);
    } else {
        gemm_tile(x, Wv, DD, (tile - 34) * 64,
                  &g_part[ks][0][2176 + (tile - 34) * 64], 2304, kc0);
    }
}

__global__ void __launch_bounds__(192) qkv_reduce(const float* __restrict__ bq,
                                                  const float* __restrict__ bk,
                                                  const float* __restrict__ bv) {
    const int b = blockIdx.x;
    const int i = blockIdx.y * 192 + threadIdx.x;
    const int c = i * 4;
    float4 s = make_float4(0.f, 0.f, 0.f, 0.f);
#pragma unroll
    for (int ks = 0; ks < KSPLIT; ks++) {
        float4 p = *(const float4*)&g_part[ks][b][c];
        s.x += p.x; s.y += p.y; s.z += p.z; s.w += p.w;
    }
    if (c < 2048) {
        float4 bb = *(const float4*)&bq[c];
        s.x += bb.x; s.y += bb.y; s.z += bb.z; s.w += bb.w;
        *(float4*)&g_q[b][c] = s;
    } else if (c < 2176) {
        float4 bb = *(const float4*)&bk[c - 2048];
        s.x += bb.x; s.y += bb.y; s.z += bb.z; s.w += bb.w;
        *(float4*)&g_kn[b][c - 2048] = s;
    } else {
        float4 bb = *(const float4*)&bv[c - 2176];
        s.x += bb.x; s.y += bb.y; s.z += bb.z; s.w += bb.w;
        *(float4*)&g_vn[b][c - 2176] = s;
    }
}

__global__ void __launch_bounds__(256) combine_kernel() {
    const int b = blockIdx.x;
    const int i = blockIdx.y * 256 + threadIdx.x;
    const int h = i >> 5;
    const int dq = (i & 31) * 4;
    float M = -1e30f;
#pragma unroll
    for (int cc = 0; cc < NSPLIT; cc++) M = fmaxf(M, g_pm[b][cc][h]);
    float den = 0.f;
    float e[NSPLIT];
#pragma unroll
    for (int cc = 0; cc < NSPLIT; cc++) {
        e[cc] = __expf(g_pm[b][cc][h] - M);
        den += e[cc] * g_pl[b][cc][h];
    }
    float inv = 1.f / den;
    float4 acc = make_float4(0.f, 0.f, 0.f, 0.f);
#pragma unroll
    for (int cc = 0; cc < NSPLIT; cc++) {
        float wgt = e[cc] * inv;
        float4 p = *(const float4*)&g_po[b][cc][h][dq];
        acc.x += wgt * p.x; acc.y += wgt * p.y;
        acc.z += wgt * p.z; acc.w += wgt * p.w;
    }
    *(float4*)&g_attn[b][h * DD + dq] = acc;
}

__global__ void __launch_bounds__(128) oproj_kernel(const float* __restrict__ Wo) {
    const int tile = blockIdx.x;
    const int ks = blockIdx.y;
    gemm_tile(&g_attn[0][0], Wo, EE, tile * 64, &g_part2[ks][0][tile * 64], EE,
              ks * KCH);
}

__global__ void __launch_bounds__(256) oproj_reduce(const float* __restrict__ bo,
                                                    float* __restrict__ out) {
    const int b = blockIdx.x;
    const int i = blockIdx.y * 256 + threadIdx.x;
    const int cq = i * 4;
    float4 s = make_float4(0.f, 0.f, 0.f, 0.f);
#pragma unroll
    for (int ks = 0; ks < KSPLIT; ks++) {
        float4 p = *(const float4*)&g_part2[ks][b][cq];
        s.x += p.x; s.y += p.y; s.z += p.z; s.w += p.w;
    }
    float4 bb = *(const float4*)&bo[cq];
    s.x += bb.x; s.y += bb.y; s.z += bb.z; s.w += bb.w;
    *(float4*)&out[(size_t)b * EE + cq] = s;
}

extern "C" void kernel_launch(void* const* d_in, const int* in_sizes, int n_in,
                              void* d_out, int out_size) {
    const float* x  = (const float*)d_in[0];
    const float* kc = (const float*)d_in[1];
    const float* vc = (const float*)d_in[2];
    const int* pos  = (const int*)d_in[3];
    const float* Wq = (const float*)d_in[4];
    const float* bq = (const float*)d_in[5];
    const float* Wk = (const float*)d_in[6];
    const float* bk = (const float*)d_in[7];
    const float* Wv = (const float*)d_in[8];
    const float* bv = (const float*)d_in[9];
    const float* Wo = (const float*)d_in[10];
    const float* bo = (const float*)d_in[11];
    float* out = (float*)d_out;

    cudaFuncSetAttribute(attn_kernel, cudaFuncAttributeMaxDynamicSharedMemorySize,
                         SMEM_ATTN);

    qkv_kernel<<<dim3(36, KSPLIT), 128>>>(x, Wq, Wk, Wv);            // 1
    qkv_reduce<<<dim3(BB, 3), 192>>>(bq, bk, bv);                    // 2
    noop_kernel<<<1, 32>>>();                                        // 3
    attn_kernel<<<dim3(NSPLIT, BB), 256, SMEM_ATTN>>>(kc, vc, pos);  // 4 (ncu)
    combine_kernel<<<dim3(BB, 2), 256>>>();                          // 5
    oproj_kernel<<<dim3(32, KSPLIT), 128>>>(Wo);                     // 6
    oproj_reduce<<<dim3(BB, 2), 256>>>(bo, out);                     // 7
}